// round 9
// baseline (speedup 1.0000x reference)
#include <cuda_runtime.h>
#include <cstdint>
#include <math.h>

// ---------------- problem constants ----------------
#define NS    5
#define NG    70
#define NBC   40
#define HP    150          // padded grid (70 + 2*40)
#define NT    1000
#define ISZ   41           // source row (padded coords)
#define IGZ   41           // receiver row
#define SW    160          // smem row stride (floats); interior col j at x=j+4
#define CW    152          // coeff row stride
#define GPR   38           // 4-wide groups per row
#define CLUSTER 8
#define TPB   768
#define MAXNR 19
#define ROWS_S (MAXNR + 4)     // 23 smem rows per CTA (2 halo each side)

#define FIELD_FLOATS (ROWS_S * SW)                           // 3680
#define MBAR_OFF (2 * FIELD_FLOATS + 3 * MAXNR * CW + NT)    // float idx of mbars
#define SMEM_FLOATS (MBAR_OFF + 4)
#define SMEM_BYTES  (SMEM_FLOATS * 4)

__device__ float g_temp1[2 * HP * CW];
__device__ float g_temp2[2 * HP * CW];
__device__ float g_alpha[2 * HP * CW];
__device__ float g_src[NT];
__device__ float g_bsrc[2 * NS];

__constant__ int c_isx[NS]        = {40, 57, 74, 92, 109};
__constant__ int c_start[CLUSTER] = {0, 19, 38, 57, 76, 95, 114, 132};
__constant__ int c_nr[CLUSTER]    = {19, 19, 19, 19, 19, 19, 18, 18};

// ---------------- ptx helpers ----------------
__device__ __forceinline__ unsigned int smem_u32(const void* p) {
    return (unsigned int)__cvta_generic_to_shared(p);
}
__device__ __forceinline__ unsigned int mapa_u32(unsigned int a, unsigned int r) {
    unsigned int d;
    asm("mapa.shared::cluster.u32 %0, %1, %2;" : "=r"(d) : "r"(a), "r"(r));
    return d;
}
__device__ __forceinline__ unsigned int my_ctarank() {
    unsigned int r;
    asm("mov.u32 %0, %%cluster_ctarank;" : "=r"(r));
    return r;
}
__device__ __forceinline__ void st2_cluster(unsigned int a, float x, float y) {
    asm volatile("st.shared::cluster.v2.f32 [%0], {%1, %2};"
                 :: "r"(a), "f"(x), "f"(y) : "memory");
}
__device__ __forceinline__ void mbar_init(unsigned int a, unsigned int count) {
    asm volatile("mbarrier.init.shared.b64 [%0], %1;" :: "r"(a), "r"(count) : "memory");
}
__device__ __forceinline__ void mbar_arrive_remote(unsigned int a) {
    asm volatile("mbarrier.arrive.release.cluster.shared::cluster.b64 _, [%0];"
                 :: "r"(a) : "memory");
}
__device__ __forceinline__ void mbar_wait_parity(unsigned int a, int parity) {
    unsigned int done;
    asm volatile(
        "{\n\t.reg .pred p;\n\t"
        "mbarrier.try_wait.parity.acquire.cluster.shared::cta.b64 p, [%1], %2;\n\t"
        "selp.b32 %0, 1, 0, p;\n\t}"
        : "=r"(done) : "r"(a), "r"((unsigned int)parity) : "memory");
    while (!done) {
        asm volatile(
            "{\n\t.reg .pred p;\n\t"
            "mbarrier.try_wait.parity.acquire.cluster.shared::cta.b64 p, [%1], %2, 0x989680;\n\t"
            "selp.b32 %0, 1, 0, p;\n\t}"
            : "=r"(done) : "r"(a), "r"((unsigned int)parity) : "memory");
    }
}

// ---------------- init: coefficients, source wavelet, bsrc ----------------
__global__ void fwi_init(const float* __restrict__ v) {
    const int b   = blockIdx.x;          // 0..1
    const int tid = threadIdx.x;         // 256 threads
    __shared__ float red[256];

    const float* vb = v + b * 70 * 70;

    float m = 1e30f;
    for (int k = tid; k < 70 * 70; k += 256) m = fminf(m, vb[k]);
    red[tid] = m;
    __syncthreads();
    for (int s = 128; s > 0; s >>= 1) {
        if (tid < s) red[tid] = fminf(red[tid], red[tid + s]);
        __syncthreads();
    }
    const float vmin  = red[0];
    const float kappa = ((3.0f * vmin) * 16.118095650958319f) / 780.0f;

    for (int k = tid; k < HP * CW; k += 256) {
        const int i = k / CW;
        const int j = k - i * CW;
        float t1 = 0.f, t2 = 0.f, al = 0.f;
        if (j < HP) {
            const int vi = min(max(i - NBC, 0), 69);
            const int vj = min(max(j - NBC, 0), 69);
            const float vp = vb[vi * 70 + vj];
            const float a  = vp * 0.001f / 10.0f;
            al = a * a;
            float r2 = 0.f;
            int rk = -1;
            if      (j < NBC)        rk = (NBC - 1) - j;
            else if (j >= HP - NBC)  rk = j - (HP - NBC);
            else if (i < NBC)        rk = (NBC - 1) - i;
            else if (i >= HP - NBC)  rk = i - (HP - NBC);
            if (rk >= 0) {
                const float t = ((float)rk * 10.0f) / 390.0f;
                r2 = t * t;
            }
            const float kdt = (kappa * r2) * 0.001f;
            t1 = 2.0f - 5.0f * al - kdt;
            t2 = 1.0f - kdt;
        }
        const int off = b * HP * CW + k;
        g_temp1[off] = t1;
        g_temp2[off] = t2;
        g_alpha[off] = al;
    }

    if (tid < NS) {
        const int isxs = c_isx[tid];
        const int vi = min(max(ISZ  - NBC, 0), 69);
        const int vj = min(max(isxs - NBC, 0), 69);
        const float bv = vb[vi * 70 + vj] * 0.001f;
        g_bsrc[b * NS + tid] = bv * bv;
    }

    if (b == 0) {
        for (int t = tid; t < NT; t += 256) {
            float w = 0.f;
            if (t < 147) {
                const double a  = (73.0 - (double)t) * 15.0 * 0.001 * 3.141592653589793;
                const double be = a * a;
                w = (float)((1.0 - 2.0 * be) * exp(-be));
            }
            g_src[t] = w;
        }
    }
}

// ---------------- main: 8-CTA cluster per (b,s) field ----------------
__global__ void __launch_bounds__(TPB, 1) __cluster_dims__(CLUSTER, 1, 1)
fwi_kernel(float* __restrict__ out) {
    extern __shared__ float sm[];
    float* buf0 = sm;
    float* buf1 = sm + FIELD_FLOATS;
    float* sT1  = sm + 2 * FIELD_FLOATS;
    float* sT2  = sT1 + MAXNR * CW;
    float* sAL  = sT2 + MAXNR * CW;
    float* srcs = sAL + MAXNR * CW;

    const int tid  = threadIdx.x;
    const int cid  = blockIdx.x / CLUSTER;
    const unsigned int rank = my_ctarank();
    const int b = cid / NS, s = cid - b * NS;

    const int start = c_start[rank];
    const int nr    = c_nr[rank];
    const unsigned int rp = (rank + CLUSTER - 1) & (CLUSTER - 1);
    const unsigned int rn = (rank + 1) & (CLUSTER - 1);
    const int nr_p = c_nr[rp];

    const unsigned int mb_u = smem_u32(sm + MBAR_OFF);
    const unsigned int b0_u = smem_u32(buf0);
    const unsigned int b1_u = smem_u32(buf1);

    // ---- init smem: zero fields, copy coeff slice + wavelet, init mbarriers ----
    for (int k = tid; k < 2 * FIELD_FLOATS; k += TPB) sm[k] = 0.f;
    {
        const float* GT1 = g_temp1 + (b * HP + start) * CW;
        const float* GT2 = g_temp2 + (b * HP + start) * CW;
        const float* GAL = g_alpha + (b * HP + start) * CW;
        const int n = nr * CW;
        for (int k = tid; k < n; k += TPB) {
            sT1[k] = GT1[k];
            sT2[k] = GT2[k];
            sAL[k] = GAL[k];
        }
        for (int k = tid; k < NT; k += TPB) srcs[k] = g_src[k];
    }
    if (tid == 0) {
        mbar_init(mb_u + 0, 2);   // full[buffer 0]: 2 neighbor arrivals per use
        mbar_init(mb_u + 8, 2);   // full[buffer 1]
        asm volatile("fence.mbarrier_init.release.cluster;" ::: "memory");
    }
    __syncthreads();

    // ---- per-thread geometry: boundary rows mapped to slots 0..3 (warps 0-4) ----
    const int slot = tid / GPR;
    const int g    = tid - slot * GPR;
    const int j0   = g * 4;
    const bool active = (slot < nr);
    int i;
    if (slot < 2)      i = slot;            // rows 0,1        (push to prev)
    else if (slot < 4) i = nr - 4 + slot;   // rows nr-2,nr-1  (push to next)
    else               i = slot - 2;        // interior rows 2..nr-3

    const int boff = (i + 2) * SW + j0;  // float index of x=j0 (logical j0-4)
    const int cb   = i * CW + j0;

    const bool pushP = active && (slot < 2);
    const bool pushN = active && (slot >= 2) && (slot < 4);
    const bool lastg = (g == GPR - 1);
    const unsigned int ppo = (unsigned int)(((nr_p + 2 + i) * SW + j0 + 4) * 4);
    const unsigned int pno = (unsigned int)(((i - (nr - 2)) * SW + j0 + 4) * 4);

    // hoist loop-invariant coefficients into registers
    float4 t1v = make_float4(0, 0, 0, 0);
    float4 t2v = t1v, alv = t1v;
    if (active) {
        t1v = *(const float4*)(sT1 + cb);
        t2v = *(const float4*)(sT2 + cb);
        alv = *(const float4*)(sAL + cb);
    }

    asm volatile("barrier.cluster.arrive.aligned;" ::: "memory");
    asm volatile("barrier.cluster.wait.aligned;"   ::: "memory");

    // remote bases (per target buffer)
    const unsigned int prevB0 = mapa_u32(b0_u, rp), prevB1 = mapa_u32(b1_u, rp);
    const unsigned int nextB0 = mapa_u32(b0_u, rn), nextB1 = mapa_u32(b1_u, rn);
    const unsigned int mprev0 = mapa_u32(mb_u, rp), mprev1 = mapa_u32(mb_u + 8, rp);
    const unsigned int mnext0 = mapa_u32(mb_u, rn), mnext1 = mapa_u32(mb_u + 8, rn);

    const int  li_src  = (ISZ >= start && ISZ < start + nr) ? (ISZ - start) : -1000;
    const int  isxs    = c_isx[s];
    const int  dsel    = isxs - j0;
    const bool srcflag = active && (i == li_src) && (dsel >= 0) && (dsel < 4);

    const bool recflag = (IGZ >= start && IGZ < start + nr) && (tid < NG);
    const int  rec_off = (IGZ - start + 2) * SW + 4 + NBC + tid;
    const float bsrcv = g_bsrc[b * NS + s];
    float* __restrict__ orow = out + (size_t)(b * NS + s) * NT * NG;

    const float C2v = (float)( 4.0 / 3.0);
    const float C3v = (float)(-1.0 / 12.0);

    // register time-cache of this thread's 4 cells: cur = p(t), old = p(t-1)
    float cur0 = 0.f, cur1 = 0.f, cur2 = 0.f, cur3 = 0.f;
    float old0 = 0.f, old1 = 0.f, old2 = 0.f, old3 = 0.f;

    // One sub-step with compile-time-fixed buffer roles. PCUR/PNEW are
    // loop-invariant base pointers -> all LDS/STS get immediate offsets.
#define FWI_STEP(PCUR, PNEW, PREVB, NEXTB, MPREV, MNEXT, MBWAIT, PAR, T)       \
    {                                                                          \
        const float srcval = bsrcv * srcs[(T)];                                \
        if (active) {                                                          \
            const float2 eL  = *(const float2*)((PCUR) + boff + 2);            \
            const float2 eR  = *(const float2*)((PCUR) + boff + 8);            \
            const float4 zm2 = *(const float4*)((PCUR) + boff - 2 * SW + 4);   \
            const float4 zm1 = *(const float4*)((PCUR) + boff -     SW + 4);   \
            const float4 zp1 = *(const float4*)((PCUR) + boff +     SW + 4);   \
            const float4 zp2 = *(const float4*)((PCUR) + boff + 2 * SW + 4);   \
            float cc6 = cur2, cc7 = cur3;                                      \
            if (lastg) {                                                       \
                const float2 eM = *(const float2*)((PCUR) + boff + 6);         \
                cc6 = eM.x; cc7 = eM.y;                                        \
            }                                                                  \
            const float cc2 = eL.x, cc3 = eL.y;                                \
            const float cc4 = cur0, cc5 = cur1;                                \
            const float cc8 = eR.x, cc9 = eR.y;                                \
            const float l0 = C2v * (cc3 + cc5 + zm1.x + zp1.x)                 \
                           + C3v * (cc2 + cc6 + zm2.x + zp2.x);                \
            const float l1 = C2v * (cc4 + cc6 + zm1.y + zp1.y)                 \
                           + C3v * (cc3 + cc7 + zm2.y + zp2.y);                \
            const float l2 = C2v * (cc5 + cc7 + zm1.z + zp1.z)                 \
                           + C3v * (cc4 + cc8 + zm2.z + zp2.z);                \
            const float l3 = C2v * (cc6 + cc8 + zm1.w + zp1.w)                 \
                           + C3v * (cc5 + cc9 + zm2.w + zp2.w);                \
            float n0 = t1v.x * cc4 - t2v.x * old0 + alv.x * l0;                \
            float n1 = t1v.y * cc5 - t2v.y * old1 + alv.y * l1;                \
            float n2 = t1v.z * cc6 - t2v.z * old2 + alv.z * l2;                \
            float n3 = t1v.w * cc7 - t2v.w * old3 + alv.w * l3;                \
            if (srcflag) {                                                     \
                if      (dsel == 0) n0 += srcval;                              \
                else if (dsel == 1) n1 += srcval;                              \
                else if (dsel == 2) n2 += srcval;                              \
                else                n3 += srcval;                              \
            }                                                                  \
            if (lastg) {                                                       \
                *(float2*)((PNEW) + boff + 4)      = make_float2(n0, n1);      \
                *(float2*)((PNEW) + boff - j0 + 2) = make_float2(n0, n1);      \
            } else {                                                           \
                *(float4*)((PNEW) + boff + 4) = make_float4(n0, n1, n2, n3);   \
                if (g == 0)                                                    \
                    *(float2*)((PNEW) + boff + 154) = make_float2(n0, n1);     \
            }                                                                  \
            if (pushP) {                                                       \
                st2_cluster((PREVB) + ppo,     n0, n1);                        \
                st2_cluster((PREVB) + ppo + 8, n2, n3);                        \
            } else if (pushN) {                                                \
                st2_cluster((NEXTB) + pno,     n0, n1);                        \
                st2_cluster((NEXTB) + pno + 8, n2, n3);                        \
            }                                                                  \
            old0 = cur0; old1 = cur1; old2 = cur2; old3 = cur3;                \
            cur0 = n0;   cur1 = n1;   cur2 = n2;   cur3 = n3;                  \
        }                                                                      \
        if (tid < 192) {                                                       \
            asm volatile("bar.sync 1, 192;" ::: "memory");                     \
            if (tid == 0)       mbar_arrive_remote(MPREV);                     \
            else if (tid == 32) mbar_arrive_remote(MNEXT);                     \
        }                                                                      \
        __syncthreads();                                                       \
        if (recflag) orow[(T) * NG + tid] = (PNEW)[rec_off];                   \
        mbar_wait_parity((MBWAIT), (PAR));                                     \
    }

    for (int t2 = 0; t2 < NT / 2; ++t2) {
        const int par = t2 & 1;
        const int te  = 2 * t2;
        // even step: pcur=buf1, pnew=buf0 (W=0)
        FWI_STEP(buf1, buf0, prevB0, nextB0, mprev0, mnext0, mb_u + 0, par, te);
        // odd step: pcur=buf0, pnew=buf1 (W=1)
        FWI_STEP(buf0, buf1, prevB1, nextB1, mprev1, mnext1, mb_u + 8, par, te + 1);
    }
#undef FWI_STEP

    asm volatile("barrier.cluster.arrive.aligned;" ::: "memory");
    asm volatile("barrier.cluster.wait.aligned;"   ::: "memory");
}

// ---------------- launch ----------------
extern "C" void kernel_launch(void* const* d_in, const int* in_sizes, int n_in,
                              void* d_out, int out_size) {
    const float* v = (const float*)d_in[0];
    float* out = (float*)d_out;

    cudaFuncSetAttribute(fwi_kernel, cudaFuncAttributeMaxDynamicSharedMemorySize,
                         SMEM_BYTES);

    fwi_init<<<2, 256>>>(v);
    fwi_kernel<<<2 * NS * CLUSTER, TPB, SMEM_BYTES>>>(out);
}

// round 10
// speedup vs baseline: 1.0084x; 1.0084x over previous
#include <cuda_runtime.h>
#include <cstdint>
#include <math.h>

// ---------------- problem constants ----------------
#define NS    5
#define NG    70
#define NBC   40
#define HP    150          // padded grid (70 + 2*40)
#define NT    1000
#define ISZ   41           // source row (padded coords)
#define IGZ   41           // receiver row
#define SW    160          // smem row stride (floats); logical col j at x=j+4
#define CW    152          // coeff row stride
#define GPR   38           // 4-wide groups per row
#define CLUSTER 8
#define TPB   896
#define MAXNR 19
#define CROWS   (MAXNR + 4)    // 23 coeff rows  (rows -2..nr+1)
#define ROWS_S2 (MAXNR + 8)    // 27 field rows  (rows -4..nr+3)

#define FIELD2    (ROWS_S2 * SW)            // 4320
#define COEFF_OFF (2 * FIELD2)              // 8640
#define SRC_OFF   (COEFF_OFF + 3 * CROWS * CW)
#define MBAR_OFF2 (SRC_OFF + NT)            // 20128 (8B aligned)
#define SMEM_FLOATS2 (MBAR_OFF2 + 4)
#define SMEM_BYTES2  (SMEM_FLOATS2 * 4)

__device__ float g_temp1[2 * HP * CW];
__device__ float g_temp2[2 * HP * CW];
__device__ float g_alpha[2 * HP * CW];
__device__ float g_src[NT];
__device__ float g_bsrc[2 * NS];

__constant__ int c_isx[NS]        = {40, 57, 74, 92, 109};
__constant__ int c_start[CLUSTER] = {0, 19, 38, 57, 76, 95, 114, 132};
__constant__ int c_nr[CLUSTER]    = {19, 19, 19, 19, 19, 19, 18, 18};

// ---------------- ptx helpers ----------------
__device__ __forceinline__ unsigned int smem_u32(const void* p) {
    return (unsigned int)__cvta_generic_to_shared(p);
}
__device__ __forceinline__ unsigned int mapa_u32(unsigned int a, unsigned int r) {
    unsigned int d;
    asm("mapa.shared::cluster.u32 %0, %1, %2;" : "=r"(d) : "r"(a), "r"(r));
    return d;
}
__device__ __forceinline__ unsigned int my_ctarank() {
    unsigned int r;
    asm("mov.u32 %0, %%cluster_ctarank;" : "=r"(r));
    return r;
}
__device__ __forceinline__ void st2_cluster(unsigned int a, float x, float y) {
    asm volatile("st.shared::cluster.v2.f32 [%0], {%1, %2};"
                 :: "r"(a), "f"(x), "f"(y) : "memory");
}
__device__ __forceinline__ void mbar_init(unsigned int a, unsigned int count) {
    asm volatile("mbarrier.init.shared.b64 [%0], %1;" :: "r"(a), "r"(count) : "memory");
}
__device__ __forceinline__ void mbar_arrive_remote(unsigned int a) {
    asm volatile("mbarrier.arrive.release.cluster.shared::cluster.b64 _, [%0];"
                 :: "r"(a) : "memory");
}
__device__ __forceinline__ void mbar_wait_parity(unsigned int a, int parity) {
    unsigned int done;
    asm volatile(
        "{\n\t.reg .pred p;\n\t"
        "mbarrier.try_wait.parity.acquire.cluster.shared::cta.b64 p, [%1], %2;\n\t"
        "selp.b32 %0, 1, 0, p;\n\t}"
        : "=r"(done) : "r"(a), "r"((unsigned int)parity) : "memory");
    while (!done) {
        asm volatile(
            "{\n\t.reg .pred p;\n\t"
            "mbarrier.try_wait.parity.acquire.cluster.shared::cta.b64 p, [%1], %2, 0x989680;\n\t"
            "selp.b32 %0, 1, 0, p;\n\t}"
            : "=r"(done) : "r"(a), "r"((unsigned int)parity) : "memory");
    }
}

// ---------------- init: coefficients, source wavelet, bsrc ----------------
__global__ void fwi_init(const float* __restrict__ v) {
    const int b   = blockIdx.x;
    const int tid = threadIdx.x;
    __shared__ float red[256];

    const float* vb = v + b * 70 * 70;

    float m = 1e30f;
    for (int k = tid; k < 70 * 70; k += 256) m = fminf(m, vb[k]);
    red[tid] = m;
    __syncthreads();
    for (int s = 128; s > 0; s >>= 1) {
        if (tid < s) red[tid] = fminf(red[tid], red[tid + s]);
        __syncthreads();
    }
    const float vmin  = red[0];
    const float kappa = ((3.0f * vmin) * 16.118095650958319f) / 780.0f;

    for (int k = tid; k < HP * CW; k += 256) {
        const int i = k / CW;
        const int j = k - i * CW;
        float t1 = 0.f, t2 = 0.f, al = 0.f;
        if (j < HP) {
            const int vi = min(max(i - NBC, 0), 69);
            const int vj = min(max(j - NBC, 0), 69);
            const float vp = vb[vi * 70 + vj];
            const float a  = vp * 0.001f / 10.0f;
            al = a * a;
            float r2 = 0.f;
            int rk = -1;
            if      (j < NBC)        rk = (NBC - 1) - j;
            else if (j >= HP - NBC)  rk = j - (HP - NBC);
            else if (i < NBC)        rk = (NBC - 1) - i;
            else if (i >= HP - NBC)  rk = i - (HP - NBC);
            if (rk >= 0) {
                const float t = ((float)rk * 10.0f) / 390.0f;
                r2 = t * t;
            }
            const float kdt = (kappa * r2) * 0.001f;
            t1 = 2.0f - 5.0f * al - kdt;
            t2 = 1.0f - kdt;
        }
        const int off = b * HP * CW + k;
        g_temp1[off] = t1;
        g_temp2[off] = t2;
        g_alpha[off] = al;
    }

    if (tid < NS) {
        const int isxs = c_isx[tid];
        const int vi = min(max(ISZ  - NBC, 0), 69);
        const int vj = min(max(isxs - NBC, 0), 69);
        const float bv = vb[vi * 70 + vj] * 0.001f;
        g_bsrc[b * NS + tid] = bv * bv;
    }

    if (b == 0) {
        for (int t = tid; t < NT; t += 256) {
            float w = 0.f;
            if (t < 147) {
                const double a  = (73.0 - (double)t) * 15.0 * 0.001 * 3.141592653589793;
                const double be = a * a;
                w = (float)((1.0 - 2.0 * be) * exp(-be));
            }
            g_src[t] = w;
        }
    }
}

// ---------------- main: 8-CTA cluster, 2 steps per halo exchange ----------------
__global__ void __launch_bounds__(TPB, 1) __cluster_dims__(CLUSTER, 1, 1)
fwi_kernel(float* __restrict__ out) {
    extern __shared__ float sm[];
    float* Bf  = sm;                    // even-t field  p(2k)   rows -4..nr+3
    float* Af  = sm + FIELD2;           // odd-t field   p(2k+1) rows -2..nr+1
    float* sT1 = sm + COEFF_OFF;
    float* sT2 = sT1 + CROWS * CW;
    float* sAL = sT2 + CROWS * CW;
    float* srcs = sm + SRC_OFF;

    const int tid  = threadIdx.x;
    const int cid  = blockIdx.x / CLUSTER;
    const unsigned int rank = my_ctarank();
    const int b = cid / NS, s = cid - b * NS;

    const int start = c_start[rank];
    const int nr    = c_nr[rank];
    const unsigned int rp = (rank + CLUSTER - 1) & (CLUSTER - 1);
    const unsigned int rn = (rank + 1) & (CLUSTER - 1);
    const int nr_p = c_nr[rp];

    const unsigned int mb_u = smem_u32(sm + MBAR_OFF2);
    const unsigned int bB_u = smem_u32(Bf);

    // ---- init smem ----
    for (int k = tid; k < 2 * FIELD2; k += TPB) sm[k] = 0.f;
    for (int k = tid; k < CROWS * CW; k += TPB) {
        const int crow = k / CW;
        const int col  = k - crow * CW;
        int grow = start + crow - 2;
        grow = (grow + HP) % HP;                 // periodic in z
        const int si = (b * HP + grow) * CW + col;
        sT1[k] = g_temp1[si];
        sT2[k] = g_temp2[si];
        sAL[k] = g_alpha[si];
    }
    for (int k = tid; k < NT; k += TPB) srcs[k] = g_src[k];
    if (tid == 0) {
        mbar_init(mb_u + 0, 2);   // mbarE: "targets of my pushes are free"
        mbar_init(mb_u + 8, 2);   // mbarF: "my ext halos are filled"
        asm volatile("fence.mbarrier_init.release.cluster;" ::: "memory");
    }
    __syncthreads();
    asm volatile("barrier.cluster.arrive.aligned;" ::: "memory");
    asm volatile("barrier.cluster.wait.aligned;"   ::: "memory");

    // remote addresses
    const unsigned int prevB  = mapa_u32(bB_u, rp);
    const unsigned int nextB  = mapa_u32(bB_u, rn);
    const unsigned int mprevE = mapa_u32(mb_u + 0, rp);
    const unsigned int mnextE = mapa_u32(mb_u + 0, rn);
    const unsigned int mprevF = mapa_u32(mb_u + 8, rp);
    const unsigned int mnextF = mapa_u32(mb_u + 8, rn);

    // ---- per-thread geometry ----
    const int slot = tid / GPR;
    const int g    = tid - slot * GPR;
    const int j0   = g * 4;
    const bool activeT = (slot < nr + 4);
    int row;
    if (slot < 6)       row = slot - 2;          // rows -2..3
    else if (slot < 12) row = nr - 10 + slot;    // rows nr-4..nr+1
    else                row = slot - 8;          // rows 4..nr-5
    const bool isExt = activeT && (row < 0 || row >= nr);
    const bool oddA  = activeT && !isExt;
    const bool pushP = activeT && (row >= 0) && (row <= 3);
    const bool pushN = activeT && (row >= nr - 4) && (row <= nr - 1);
    const bool lastg = (g == GPR - 1);
    const bool g0    = (g == 0);

    const int boff = (row + 4) * SW + j0;  // x=j0 (logical col j0-4)
    const int cb   = (row + 2) * CW + j0;

    unsigned int pBase = 0, pMir = 0, nBase = 0, nMir = 0;
    if (pushP) {
        const int trow = nr_p + row + 4;
        pBase = prevB + (unsigned int)((trow * SW + j0 + 4) * 4);
        pMir  = prevB + (unsigned int)((trow * SW + (g0 ? 154 : 2)) * 4);
    }
    if (pushN) {
        const int trow = row - nr + 4;
        nBase = nextB + (unsigned int)((trow * SW + j0 + 4) * 4);
        nMir  = nextB + (unsigned int)((trow * SW + (g0 ? 154 : 2)) * 4);
    }

    float4 t1v = make_float4(0, 0, 0, 0);
    float4 t2v = t1v, alv = t1v;
    if (activeT) {
        t1v = *(const float4*)(sT1 + cb);
        t2v = *(const float4*)(sT2 + cb);
        alv = *(const float4*)(sAL + cb);
    }

    const int  isxs    = c_isx[s];
    const int  dsel    = isxs - j0;
    const bool srcflag = activeT && (start + row == ISZ) && (dsel >= 0) && (dsel < 4);
    const bool recflag = (IGZ >= start && IGZ < start + nr) && (tid < NG);
    const int  rec_off = (IGZ - start + 4) * SW + 4 + NBC + tid;
    const float bsrcv = g_bsrc[b * NS + s];
    float* __restrict__ orow = out + (size_t)(b * NS + s) * NT * NG;

    const float C2v = (float)( 4.0 / 3.0);
    const float C3v = (float)(-1.0 / 12.0);

    // register time-cache (interior rows): cur = p(2k), old = p(2k-1)
    float cur0 = 0.f, cur1 = 0.f, cur2 = 0.f, cur3 = 0.f;
    float old0 = 0.f, old1 = 0.f, old2 = 0.f, old3 = 0.f;

    for (int k = 0; k < NT / 2; ++k) {
        const int par = k & 1;

        // ======== EVEN: p(2k+1) on rows [-2, nr+2) -> A ========
        {
            const float se = bsrcv * srcs[2 * k];
            if (activeT) {
                const float2 eL  = *(const float2*)(Bf + boff + 2);
                const float2 eR  = *(const float2*)(Bf + boff + 8);
                const float4 zm2 = *(const float4*)(Bf + boff - 2 * SW + 4);
                const float4 zm1 = *(const float4*)(Bf + boff -     SW + 4);
                const float4 zp1 = *(const float4*)(Bf + boff +     SW + 4);
                const float4 zp2 = *(const float4*)(Bf + boff + 2 * SW + 4);

                float cc4, cc5, cc6, cc7, o0, o1, o2, o3;
                if (isExt) {
                    const float4 cB = *(const float4*)(Bf + boff + 4);
                    const float4 oA = *(const float4*)(Af + boff + 4);
                    cc4 = cB.x; cc5 = cB.y; cc6 = cB.z; cc7 = cB.w;
                    o0 = oA.x; o1 = oA.y; o2 = oA.z; o3 = oA.w;
                } else {
                    cc4 = cur0; cc5 = cur1; cc6 = cur2; cc7 = cur3;
                    o0 = old0; o1 = old1; o2 = old2; o3 = old3;
                    if (lastg) {
                        const float2 eM = *(const float2*)(Bf + boff + 6);
                        cc6 = eM.x; cc7 = eM.y;
                    }
                }
                const float cc2 = eL.x, cc3 = eL.y;
                const float cc8 = eR.x, cc9 = eR.y;

                const float l0 = C2v * (cc3 + cc5 + zm1.x + zp1.x)
                               + C3v * (cc2 + cc6 + zm2.x + zp2.x);
                const float l1 = C2v * (cc4 + cc6 + zm1.y + zp1.y)
                               + C3v * (cc3 + cc7 + zm2.y + zp2.y);
                const float l2 = C2v * (cc5 + cc7 + zm1.z + zp1.z)
                               + C3v * (cc4 + cc8 + zm2.z + zp2.z);
                const float l3 = C2v * (cc6 + cc8 + zm1.w + zp1.w)
                               + C3v * (cc5 + cc9 + zm2.w + zp2.w);

                float n0 = t1v.x * cc4 - t2v.x * o0 + alv.x * l0;
                float n1 = t1v.y * cc5 - t2v.y * o1 + alv.y * l1;
                float n2 = t1v.z * cc6 - t2v.z * o2 + alv.z * l2;
                float n3 = t1v.w * cc7 - t2v.w * o3 + alv.w * l3;

                if (srcflag) {
                    if      (dsel == 0) n0 += se;
                    else if (dsel == 1) n1 += se;
                    else if (dsel == 2) n2 += se;
                    else                n3 += se;
                }

                if (lastg) {
                    *(float2*)(Af + boff + 4)      = make_float2(n0, n1);
                    *(float2*)(Af + boff - j0 + 2) = make_float2(n0, n1);
                } else {
                    *(float4*)(Af + boff + 4) = make_float4(n0, n1, n2, n3);
                    if (g0)
                        *(float2*)(Af + boff + 154) = make_float2(n0, n1);
                }
                if (!isExt) {
                    old0 = cur0; old1 = cur1; old2 = cur2; old3 = cur3;
                    cur0 = n0;   cur1 = n1;   cur2 = n2;   cur3 = n3;
                }
            }
            __syncthreads();                       // sync1: A complete, B-ext reads done
            if (tid == 0)       mbar_arrive_remote(mprevE);
            else if (tid == 32) mbar_arrive_remote(mnextE);
            if (recflag) orow[(2 * k) * NG + tid] = Af[rec_off];
        }

        // ======== ODD: p(2k+2) on rows [0, nr) -> B (+ pushes) ========
        {
            const float so = bsrcv * srcs[2 * k + 1];
            if (oddA) {
                const float2 eL  = *(const float2*)(Af + boff + 2);
                const float2 eR  = *(const float2*)(Af + boff + 8);
                const float4 zm2 = *(const float4*)(Af + boff - 2 * SW + 4);
                const float4 zm1 = *(const float4*)(Af + boff -     SW + 4);
                const float4 zp1 = *(const float4*)(Af + boff +     SW + 4);
                const float4 zp2 = *(const float4*)(Af + boff + 2 * SW + 4);

                float cc6 = cur2, cc7 = cur3;
                if (lastg) {
                    const float2 eM = *(const float2*)(Af + boff + 6);
                    cc6 = eM.x; cc7 = eM.y;
                }
                const float cc2 = eL.x, cc3 = eL.y;
                const float cc4 = cur0, cc5 = cur1;
                const float cc8 = eR.x, cc9 = eR.y;

                const float l0 = C2v * (cc3 + cc5 + zm1.x + zp1.x)
                               + C3v * (cc2 + cc6 + zm2.x + zp2.x);
                const float l1 = C2v * (cc4 + cc6 + zm1.y + zp1.y)
                               + C3v * (cc3 + cc7 + zm2.y + zp2.y);
                const float l2 = C2v * (cc5 + cc7 + zm1.z + zp1.z)
                               + C3v * (cc4 + cc8 + zm2.z + zp2.z);
                const float l3 = C2v * (cc6 + cc8 + zm1.w + zp1.w)
                               + C3v * (cc5 + cc9 + zm2.w + zp2.w);

                float n0 = t1v.x * cc4 - t2v.x * old0 + alv.x * l0;
                float n1 = t1v.y * cc5 - t2v.y * old1 + alv.y * l1;
                float n2 = t1v.z * cc6 - t2v.z * old2 + alv.z * l2;
                float n3 = t1v.w * cc7 - t2v.w * old3 + alv.w * l3;

                if (srcflag) {
                    if      (dsel == 0) n0 += so;
                    else if (dsel == 1) n1 += so;
                    else if (dsel == 2) n2 += so;
                    else                n3 += so;
                }

                if (lastg) {
                    *(float2*)(Bf + boff + 4)      = make_float2(n0, n1);
                    *(float2*)(Bf + boff - j0 + 2) = make_float2(n0, n1);
                } else {
                    *(float4*)(Bf + boff + 4) = make_float4(n0, n1, n2, n3);
                    if (g0)
                        *(float2*)(Bf + boff + 154) = make_float2(n0, n1);
                }
                old0 = cur0; old1 = cur1; old2 = cur2; old3 = cur3;
                cur0 = n0;   cur1 = n1;   cur2 = n2;   cur3 = n3;

                // pushes: gated on neighbors having consumed their ext halos
                if (pushP) {
                    mbar_wait_parity(mb_u + 0, par);
                    st2_cluster(pBase, n0, n1);
                    if (!lastg) st2_cluster(pBase + 8, n2, n3);
                    if (g0 || lastg) st2_cluster(pMir, n0, n1);
                } else if (pushN) {
                    mbar_wait_parity(mb_u + 0, par);
                    st2_cluster(nBase, n0, n1);
                    if (!lastg) st2_cluster(nBase + 8, n2, n3);
                    if (g0 || lastg) st2_cluster(nMir, n0, n1);
                }
            }

            // pusher-warp rendezvous, then elected F-arrivals (early, overlapped)
            if (tid >= 64 && tid < 256)
                asm volatile("bar.sync 2, 192;" ::: "memory");
            if (tid == 64)  mbar_arrive_remote(mprevF);
            if (tid >= 224 && tid < 384)
                asm volatile("bar.sync 3, 160;" ::: "memory");
            if (tid == 256) mbar_arrive_remote(mnextF);

            __syncthreads();                       // sync2: B interior complete
            if (recflag) orow[(2 * k + 1) * NG + tid] = Bf[rec_off];
            if (tid < 480) mbar_wait_parity(mb_u + 8, par);  // ext-readers only
        }
    }

    asm volatile("barrier.cluster.arrive.aligned;" ::: "memory");
    asm volatile("barrier.cluster.wait.aligned;"   ::: "memory");
}

// ---------------- launch ----------------
extern "C" void kernel_launch(void* const* d_in, const int* in_sizes, int n_in,
                              void* d_out, int out_size) {
    const float* v = (const float*)d_in[0];
    float* out = (float*)d_out;

    cudaFuncSetAttribute(fwi_kernel, cudaFuncAttributeMaxDynamicSharedMemorySize,
                         SMEM_BYTES2);

    fwi_init<<<2, 256>>>(v);
    fwi_kernel<<<2 * NS * CLUSTER, TPB, SMEM_BYTES2>>>(out);
}